// round 1
// baseline (speedup 1.0000x reference)
#include <cuda_runtime.h>
#include <math.h>

#define BS 32
#define NA 8400
#define NC 80
#define NB 64
#define TOPK 13
#define CAP 1024
#define EPSF 1e-9f
#define IOU_EPS 1e-7f

// ---------------- scratch (static device globals; no runtime alloc) ----------------
__device__ unsigned long long g_cand_key[BS * NB * CAP];   // 16 MB
__device__ float              g_cand_ov [BS * NB * CAP];   // 8 MB
__device__ int                g_cand_cnt[BS * NB];
__device__ int                g_fin_idx [BS * NB * TOPK];
__device__ float              g_fin_met [BS * NB * TOPK];
__device__ float              g_fin_ovl [BS * NB * TOPK];
__device__ int                g_cnt     [BS * NA];
__device__ int                g_candj   [BS * NA];
__device__ float              g_met_a   [BS * NA];
__device__ float              g_ov_a    [BS * NA];
__device__ int                g_assigned[BS * NA];
__device__ float              g_norm_al [BS * NA];
__device__ unsigned           g_pos_align[BS * NB];        // float bits, values >= 0
__device__ unsigned           g_pos_over [BS * NB];

__device__ __forceinline__ float ciou_f(float gx1, float gy1, float gx2, float gy2,
                                        float px1, float py1, float px2, float py2) {
    // box1 = gt, box2 = pd (matches reference ciou(gt, pd))
    float w1 = gx2 - gx1, h1 = gy2 - gy1 + IOU_EPS;
    float w2 = px2 - px1, h2 = py2 - py1 + IOU_EPS;
    float iw = fminf(gx2, px2) - fmaxf(gx1, px1);
    float ih = fminf(gy2, py2) - fmaxf(gy1, py1);
    float inter = fmaxf(iw, 0.f) * fmaxf(ih, 0.f);
    float uni = w1 * h1 + w2 * h2 - inter + IOU_EPS;
    float iou = inter / uni;
    float cw = fmaxf(gx2, px2) - fminf(gx1, px1);
    float ch = fmaxf(gy2, py2) - fminf(gy1, py1);
    float c2 = cw * cw + ch * ch + IOU_EPS;
    float dx = px1 + px2 - gx1 - gx2;
    float dy = py1 + py2 - gy1 - gy2;
    float rho2 = (dx * dx + dy * dy) * 0.25f;
    float dat = atanf(w2 / h2) - atanf(w1 / h1);
    float v = 0.4052847345693511f * dat * dat;   // 4/pi^2
    float alpha = v / (v - iou + (1.0f + IOU_EPS));
    return iou - (rho2 / c2 + v * alpha);
}

__device__ __forceinline__ float pow6(float x) { float x2 = x * x; return x2 * x2 * x2; }

// ---------------- kernel 0: zero scratch + scores region of d_out ----------------
__global__ void k_zero(float* __restrict__ out) {
    long long i = (long long)blockIdx.x * blockDim.x + threadIdx.x;
    long long stride = (long long)gridDim.x * blockDim.x;
    float4* score4 = (float4*)(out + (long long)BS * NA * 5);
    long long n4 = (long long)BS * NA * NC / 4;
    float4 z = make_float4(0.f, 0.f, 0.f, 0.f);
    for (long long k = i; k < n4; k += stride) score4[k] = z;
    for (long long k = i; k < (long long)BS * NA; k += stride) g_cnt[k] = 0;
    for (long long k = i; k < (long long)BS * NB; k += stride) {
        g_cand_cnt[k] = 0;
        g_pos_align[k] = 0u;
        g_pos_over[k] = 0u;
    }
}

// ---------------- kernel 1: candidate generation (positives) ----------------
__global__ void k_cand(const float* __restrict__ pd_scores, const float* __restrict__ pd_bboxes,
                       const float* __restrict__ anc, const int* __restrict__ gt_labels,
                       const float* __restrict__ gt_bboxes, const float* __restrict__ mask_gt) {
    int b = blockIdx.y;
    __shared__ float sgt[NB * 4];
    __shared__ float smgt[NB];
    __shared__ int   slbl[NB];
    int tid = threadIdx.x;
    for (int i = tid; i < NB * 4; i += blockDim.x) sgt[i] = gt_bboxes[b * NB * 4 + i];
    for (int i = tid; i < NB; i += blockDim.x) { smgt[i] = mask_gt[b * NB + i]; slbl[i] = gt_labels[b * NB + i]; }
    __syncthreads();
    int a = blockIdx.x * blockDim.x + tid;
    if (a >= NA) return;
    float ax = anc[a * 2 + 0], ay = anc[a * 2 + 1];
    float px1 = 0.f, py1 = 0.f, px2 = 0.f, py2 = 0.f;
    bool pl = false;
    long long pos = (long long)b * NA + a;
    for (int j = 0; j < NB; j++) {
        if (smgt[j] <= 0.f) continue;
        float gx1 = sgt[j * 4 + 0], gy1 = sgt[j * 4 + 1], gx2 = sgt[j * 4 + 2], gy2 = sgt[j * 4 + 3];
        if (!(ax - gx1 > EPSF && ay - gy1 > EPSF && gx2 - ax > EPSF && gy2 - ay > EPSF)) continue;
        if (!pl) {
            const float4 pb = *(const float4*)(pd_bboxes + pos * 4);
            px1 = pb.x; py1 = pb.y; px2 = pb.z; py2 = pb.w; pl = true;
        }
        float ov = fmaxf(ciou_f(gx1, gy1, gx2, gy2, px1, py1, px2, py2), 0.f);
        float s = pd_scores[pos * NC + slbl[j]];
        float met = s * pow6(ov);
        if (met > 0.f) {
            int row = b * NB + j;
            int slot = atomicAdd(&g_cand_cnt[row], 1);
            if (slot < CAP) {
                g_cand_key[row * CAP + slot] =
                    ((unsigned long long)__float_as_uint(met) << 32) | (unsigned)(0xFFFFFFFFu - (unsigned)a);
                g_cand_ov[row * CAP + slot] = ov;
            }
        }
    }
}

// ---------------- kernel 2: exact top-13 per (b, gt) + zero-fill semantics ----------------
__global__ void k_topk(const float* __restrict__ anc, const float* __restrict__ gt_bboxes,
                       const float* __restrict__ mask_gt) {
    int row = blockIdx.x;             // b*NB + j
    int tid = threadIdx.x;
    __shared__ unsigned long long skey[CAP];
    __shared__ unsigned long long rkey[128];
    __shared__ int rslot[128];
    if (mask_gt[row] <= 0.f) {        // mgt==0: tk indices zeroed -> cnt>1 -> no candidates
        for (int k = tid; k < TOPK; k += blockDim.x) g_fin_idx[row * TOPK + k] = -1;
        return;
    }
    int P = min(g_cand_cnt[row], CAP);
    for (int i = tid; i < P; i += blockDim.x) skey[i] = g_cand_key[row * CAP + i];
    __syncthreads();
    int nsel = min(P, TOPK);
    for (int r = 0; r < nsel; r++) {
        unsigned long long best = 0; int bslot = -1;
        for (int i = tid; i < P; i += blockDim.x)
            if (skey[i] > best) { best = skey[i]; bslot = i; }
        rkey[tid] = best; rslot[tid] = bslot;
        __syncthreads();
        for (int off = 64; off > 0; off >>= 1) {
            if (tid < off && rkey[tid + off] > rkey[tid]) { rkey[tid] = rkey[tid + off]; rslot[tid] = rslot[tid + off]; }
            __syncthreads();
        }
        if (tid == 0) {
            int sl = rslot[0];
            unsigned long long k64 = rkey[0];
            g_fin_idx[row * TOPK + r] = (int)(0xFFFFFFFFu - (unsigned)(k64 & 0xFFFFFFFFull));
            g_fin_met[row * TOPK + r] = __uint_as_float((unsigned)(k64 >> 32));
            g_fin_ovl[row * TOPK + r] = g_cand_ov[row * CAP + sl];
            skey[sl] = 0ull;
        }
        __syncthreads();
    }
    if (tid == 0) {
        int kfill = nsel;
        if (nsel < TOPK) {
            // jax.lax.top_k fills remaining slots with smallest-index zero-metric anchors;
            // they become mask_pos only if inside the gt box (then ov==0, met==0).
            float gx1 = gt_bboxes[row * 4 + 0], gy1 = gt_bboxes[row * 4 + 1];
            float gx2 = gt_bboxes[row * 4 + 2], gy2 = gt_bboxes[row * 4 + 3];
            int slots = nsel;
            int a = 0;
            while (slots < TOPK && a < NA) {
                bool ispos = false;
                for (int t = 0; t < nsel; t++)
                    if (g_fin_idx[row * TOPK + t] == a) { ispos = true; break; }
                if (!ispos) {
                    slots++;
                    float ax = anc[a * 2 + 0], ay = anc[a * 2 + 1];
                    if (ax - gx1 > EPSF && ay - gy1 > EPSF && gx2 - ax > EPSF && gy2 - ay > EPSF) {
                        g_fin_idx[row * TOPK + kfill] = a;
                        g_fin_met[row * TOPK + kfill] = 0.f;
                        g_fin_ovl[row * TOPK + kfill] = 0.f;
                        kfill++;
                    }
                }
                a++;
            }
        }
        for (int k = kfill; k < TOPK; k++) g_fin_idx[row * TOPK + k] = -1;
    }
}

// ---------------- kernel 3: scatter candidates onto anchors ----------------
__global__ void k_scatter() {
    int t = blockIdx.x * blockDim.x + threadIdx.x;
    if (t >= BS * NB * TOPK) return;
    int idx = g_fin_idx[t];
    if (idx < 0) return;
    int row = t / TOPK;
    int b = row / NB, j = row % NB;
    int pos = b * NA + idx;
    atomicAdd(&g_cnt[pos], 1);
    g_candj[pos] = j;              // races only matter when cnt>1 (value unused then)
    g_met_a[pos] = g_fin_met[t];
    g_ov_a[pos]  = g_fin_ovl[t];
}

// ---------------- kernel 4: per-anchor resolution + pos_align/pos_over ----------------
__global__ void k_resolve(const float* __restrict__ pd_scores, const float* __restrict__ pd_bboxes,
                          const float* __restrict__ anc, const int* __restrict__ gt_labels,
                          const float* __restrict__ gt_bboxes, const float* __restrict__ mask_gt) {
    int b = blockIdx.y;
    __shared__ float sgt[NB * 4];
    __shared__ float smgt[NB];
    __shared__ int   slbl[NB];
    int tid = threadIdx.x;
    for (int i = tid; i < NB * 4; i += blockDim.x) sgt[i] = gt_bboxes[b * NB * 4 + i];
    for (int i = tid; i < NB; i += blockDim.x) { smgt[i] = mask_gt[b * NB + i]; slbl[i] = gt_labels[b * NB + i]; }
    __syncthreads();
    int a = blockIdx.x * blockDim.x + tid;
    if (a >= NA) return;
    long long pos = (long long)b * NA + a;
    int c = g_cnt[pos];
    if (c == 0) { g_assigned[pos] = -1; g_norm_al[pos] = 0.f; return; }
    int jm; float met, ov;
    if (c == 1) {
        jm = g_candj[pos]; met = g_met_a[pos]; ov = g_ov_a[pos];
    } else {
        // multi-gt anchor: argmax_j overlaps (first max wins), over ALL gts
        float ax = anc[a * 2 + 0], ay = anc[a * 2 + 1];
        const float4 pb = *(const float4*)(pd_bboxes + pos * 4);
        float bestov = -1.f; int bestj = 0;
        for (int j = 0; j < NB; j++) {
            float ovj = 0.f;
            if (smgt[j] > 0.f) {
                float gx1 = sgt[j * 4 + 0], gy1 = sgt[j * 4 + 1], gx2 = sgt[j * 4 + 2], gy2 = sgt[j * 4 + 3];
                if (ax - gx1 > EPSF && ay - gy1 > EPSF && gx2 - ax > EPSF && gy2 - ay > EPSF)
                    ovj = fmaxf(ciou_f(gx1, gy1, gx2, gy2, pb.x, pb.y, pb.z, pb.w), 0.f);
            }
            if (ovj > bestov) { bestov = ovj; bestj = j; }
        }
        jm = bestj; ov = bestov;
        met = (ov > 0.f) ? pd_scores[pos * NC + slbl[jm]] * pow6(ov) : 0.f;
    }
    g_assigned[pos] = jm;
    g_norm_al[pos]  = met;
    atomicMax(&g_pos_align[b * NB + jm], __float_as_uint(met));
    atomicMax(&g_pos_over [b * NB + jm], __float_as_uint(ov));
}

// ---------------- kernel 5: write outputs ----------------
__global__ void k_out(const int* __restrict__ gt_labels, const float* __restrict__ gt_bboxes,
                      float* __restrict__ out) {
    int b = blockIdx.y;
    int a = blockIdx.x * blockDim.x + threadIdx.x;
    if (a >= NA) return;
    long long pos = (long long)b * NA + a;
    int jm = g_assigned[pos];
    bool fg = (jm >= 0);
    int j0 = fg ? jm : 0;
    int label = gt_labels[b * NB + j0];
    const float4 gb = *(const float4*)(gt_bboxes + (b * NB + j0) * 4);
    const long long L = (long long)BS * NA;
    out[pos] = (float)label;                                   // target_labels
    *(float4*)(out + L + pos * 4) = gb;                        // target_bboxes
    out[L * 5 + L * NC + pos] = fg ? 1.f : 0.f;                // fg_mask
    out[L * 6 + L * NC + pos] = (float)j0;                     // target_gt_idx
    if (fg) {
        float pa = __uint_as_float(g_pos_align[b * NB + jm]);
        float po = __uint_as_float(g_pos_over [b * NB + jm]);
        float norm = g_norm_al[pos] * po / (pa + EPSF);
        out[L * 5 + pos * NC + label] = norm;                  // target_scores (one-hot * norm)
    }
}

// ---------------- launch ----------------
extern "C" void kernel_launch(void* const* d_in, const int* in_sizes, int n_in,
                              void* d_out, int out_size) {
    const float* pd_scores = (const float*)d_in[0];
    const float* pd_bboxes = (const float*)d_in[1];
    const float* anc       = (const float*)d_in[2];
    const int*   gt_labels = (const int*)  d_in[3];
    const float* gt_bboxes = (const float*)d_in[4];
    const float* mask_gt   = (const float*)d_in[5];
    float* out = (float*)d_out;

    dim3 gridA((NA + 255) / 256, BS);

    k_zero<<<2048, 256>>>(out);
    k_cand<<<gridA, 256>>>(pd_scores, pd_bboxes, anc, gt_labels, gt_bboxes, mask_gt);
    k_topk<<<BS * NB, 128>>>(anc, gt_bboxes, mask_gt);
    k_scatter<<<(BS * NB * TOPK + 255) / 256, 256>>>();
    k_resolve<<<gridA, 256>>>(pd_scores, pd_bboxes, anc, gt_labels, gt_bboxes, mask_gt);
    k_out<<<gridA, 256>>>(gt_labels, gt_bboxes, out);
}

// round 2
// speedup vs baseline: 1.3495x; 1.3495x over previous
#include <cuda_runtime.h>
#include <math.h>

#define BS 32
#define NA 8400
#define NC 80
#define NB 64
#define TOPK 13
#define CAP 640
#define EPSF 1e-9f
#define IOU_EPS 1e-7f
#define GW 32
#define GH 32
#define BININV 0.05f   // 1/20 px

// ---------------- scratch (static device globals) ----------------
__device__ int      g_bin_start[GW * GH + 1];
__device__ int      g_abin[NA];
__device__ float    g_bax[NA];
__device__ float    g_bay[NA];
__device__ int      g_baid[NA];
__device__ int      g_cnt     [BS * NA];
__device__ int      g_candj   [BS * NA];
__device__ float    g_met_a   [BS * NA];
__device__ float    g_ov_a    [BS * NA];
__device__ int      g_assigned[BS * NA];
__device__ float    g_norm_al [BS * NA];
__device__ unsigned g_pos_align[BS * NB];   // float bits, >= 0
__device__ unsigned g_pos_over [BS * NB];

__device__ __forceinline__ float ciou_f(float gx1, float gy1, float gx2, float gy2,
                                        float px1, float py1, float px2, float py2) {
    float w1 = gx2 - gx1, h1 = gy2 - gy1 + IOU_EPS;
    float w2 = px2 - px1, h2 = py2 - py1 + IOU_EPS;
    float iw = fminf(gx2, px2) - fmaxf(gx1, px1);
    float ih = fminf(gy2, py2) - fmaxf(gy1, py1);
    float inter = fmaxf(iw, 0.f) * fmaxf(ih, 0.f);
    float uni = w1 * h1 + w2 * h2 - inter + IOU_EPS;
    float iou = inter / uni;
    float cw = fmaxf(gx2, px2) - fminf(gx1, px1);
    float ch = fmaxf(gy2, py2) - fminf(gy1, py1);
    float c2 = cw * cw + ch * ch + IOU_EPS;
    float dx = px1 + px2 - gx1 - gx2;
    float dy = py1 + py2 - gy1 - gy2;
    float rho2 = (dx * dx + dy * dy) * 0.25f;
    float dat = atanf(w2 / h2) - atanf(w1 / h1);
    float v = 0.4052847345693511f * dat * dat;
    float alpha = v / (v - iou + (1.0f + IOU_EPS));
    return iou - (rho2 / c2 + v * alpha);
}

__device__ __forceinline__ float pow6(float x) { float x2 = x * x; return x2 * x2 * x2; }

// ---------------- kernel Z: zero small scratch ----------------
__global__ void k_zeroScratch() {
    int i = blockIdx.x * blockDim.x + threadIdx.x;
    int stride = gridDim.x * blockDim.x;
    for (int k = i; k < BS * NA; k += stride) g_cnt[k] = 0;
    for (int k = i; k < BS * NB; k += stride) { g_pos_align[k] = 0u; g_pos_over[k] = 0u; }
}

// ---------------- kernel A: bin anchors (single block, 1024 threads) ----------------
__global__ void k_bins(const float* __restrict__ anc) {
    __shared__ int scnt[GW * GH];
    __shared__ int soff[GW * GH];
    int tid = threadIdx.x;
    scnt[tid] = 0;
    __syncthreads();
    for (int i = tid; i < NA; i += 1024) {
        float ax = anc[i * 2 + 0], ay = anc[i * 2 + 1];
        int bx = min(GW - 1, max(0, (int)(ax * BININV)));
        int by = min(GH - 1, max(0, (int)(ay * BININV)));
        int bin = by * GW + bx;
        g_abin[i] = bin;
        atomicAdd(&scnt[bin], 1);
    }
    __syncthreads();
    int myc = scnt[tid];
    // inclusive scan over 1024 bins
    for (int off = 1; off < 1024; off <<= 1) {
        int v = (tid >= off) ? scnt[tid - off] : 0;
        __syncthreads();
        scnt[tid] += v;
        __syncthreads();
    }
    g_bin_start[tid + 1] = scnt[tid];
    if (tid == 0) g_bin_start[0] = 0;
    soff[tid] = scnt[tid] - myc;   // exclusive
    __syncthreads();
    for (int i = tid; i < NA; i += 1024) {
        int bin = g_abin[i];
        int slot = atomicAdd(&soff[bin], 1);
        g_baid[slot] = i;
        g_bax[slot] = anc[i * 2 + 0];
        g_bay[slot] = anc[i * 2 + 1];
    }
}

// ---------------- kernel B: per-row candidates + top-13 + zero-fill + scatter ----------------
__global__ void k_rows(const float* __restrict__ pd_scores, const float* __restrict__ pd_bboxes,
                       const float* __restrict__ anc, const int* __restrict__ gt_labels,
                       const float* __restrict__ gt_bboxes, const float* __restrict__ mask_gt) {
    const int row = blockIdx.x;            // b*NB + j
    const int b = row >> 6, j = row & 63;
    const int tid = threadIdx.x;
    const int lane = tid & 31, wid = tid >> 5;

    __shared__ unsigned long long skey[CAP];
    __shared__ float sov[CAP];
    __shared__ int sP;
    __shared__ int sfidx[TOPK];
    __shared__ float sfmet[TOPK];
    __shared__ float sfovl[TOPK];
    __shared__ int skfill;
    __shared__ unsigned long long wbest[2];
    __shared__ int wslot[2];

    if (mask_gt[row] <= 0.f) return;

    if (tid == 0) sP = 0;
    __syncthreads();

    const float gx1 = gt_bboxes[row * 4 + 0], gy1 = gt_bboxes[row * 4 + 1];
    const float gx2 = gt_bboxes[row * 4 + 2], gy2 = gt_bboxes[row * 4 + 3];
    const int lbl = gt_labels[row];

    int bx_lo = min(GW - 1, max(0, (int)floorf(gx1 * BININV)));
    int bx_hi = min(GW - 1, max(0, (int)floorf(gx2 * BININV)));
    int by_lo = min(GH - 1, max(0, (int)floorf(gy1 * BININV)));
    int by_hi = min(GH - 1, max(0, (int)floorf(gy2 * BININV)));

    for (int by = by_lo; by <= by_hi; by++) {
        int s = g_bin_start[by * GW + bx_lo];
        int e = g_bin_start[by * GW + bx_hi + 1];
        for (int i = s + tid; i < e; i += 64) {
            float ax = g_bax[i], ay = g_bay[i];
            if (!(ax - gx1 > EPSF && ay - gy1 > EPSF && gx2 - ax > EPSF && gy2 - ay > EPSF)) continue;
            int a = g_baid[i];
            long long pos = (long long)b * NA + a;
            const float4 pb = __ldg((const float4*)(pd_bboxes + pos * 4));
            float ov = fmaxf(ciou_f(gx1, gy1, gx2, gy2, pb.x, pb.y, pb.z, pb.w), 0.f);
            float met = pd_scores[pos * NC + lbl] * pow6(ov);
            if (met > 0.f) {
                int slot = atomicAdd(&sP, 1);
                if (slot < CAP) {
                    skey[slot] = ((unsigned long long)__float_as_uint(met) << 32)
                               | (unsigned)(0xFFFFFFFFu - (unsigned)a);
                    sov[slot] = ov;
                }
            }
        }
    }
    __syncthreads();
    int P = min(sP, CAP);
    int nsel = min(P, TOPK);

    for (int r = 0; r < nsel; r++) {
        unsigned long long best = 0; int bslot = -1;
        for (int i = tid; i < P; i += 64)
            if (skey[i] > best) { best = skey[i]; bslot = i; }
        for (int off = 16; off > 0; off >>= 1) {
            unsigned long long ob = __shfl_down_sync(0xFFFFFFFFu, best, off);
            int os = __shfl_down_sync(0xFFFFFFFFu, bslot, off);
            if (ob > best) { best = ob; bslot = os; }
        }
        if (lane == 0) { wbest[wid] = best; wslot[wid] = bslot; }
        __syncthreads();
        if (tid == 0) {
            unsigned long long bb = wbest[0]; int bs2 = wslot[0];
            if (wbest[1] > bb) { bb = wbest[1]; bs2 = wslot[1]; }
            sfidx[r] = (int)(0xFFFFFFFFu - (unsigned)(bb & 0xFFFFFFFFull));
            sfmet[r] = __uint_as_float((unsigned)(bb >> 32));
            sfovl[r] = sov[bs2];
            skey[bs2] = 0ull;
        }
        __syncthreads();
    }

    if (tid == 0) {
        int kfill = nsel;
        if (nsel < TOPK) {
            // top_k fills remaining slots with smallest-index zero-metric anchors;
            // they survive only if inside the gt box.
            int slots = nsel;
            int a = 0;
            while (slots < TOPK && a < NA) {
                bool ispos = false;
                for (int t = 0; t < nsel; t++)
                    if (sfidx[t] == a) { ispos = true; break; }
                if (!ispos) {
                    slots++;
                    float ax = anc[a * 2 + 0], ay = anc[a * 2 + 1];
                    if (ax - gx1 > EPSF && ay - gy1 > EPSF && gx2 - ax > EPSF && gy2 - ay > EPSF) {
                        sfidx[kfill] = a; sfmet[kfill] = 0.f; sfovl[kfill] = 0.f;
                        kfill++;
                    }
                }
                a++;
            }
        }
        skfill = kfill;
    }
    __syncthreads();

    if (tid < skfill) {
        int a = sfidx[tid];
        int pos = b * NA + a;
        atomicAdd(&g_cnt[pos], 1);
        g_candj[pos] = j;            // race only matters when cnt>1 (value unused then)
        g_met_a[pos] = sfmet[tid];
        g_ov_a[pos]  = sfovl[tid];
    }
}

// ---------------- kernel C: per-anchor resolution + pos maxima ----------------
__global__ void k_resolve(const float* __restrict__ pd_scores, const float* __restrict__ pd_bboxes,
                          const float* __restrict__ anc, const int* __restrict__ gt_labels,
                          const float* __restrict__ gt_bboxes, const float* __restrict__ mask_gt) {
    int b = blockIdx.y;
    __shared__ float sgt[NB * 4];
    __shared__ float smgt[NB];
    __shared__ int   slbl[NB];
    int tid = threadIdx.x;
    for (int i = tid; i < NB * 4; i += blockDim.x) sgt[i] = gt_bboxes[b * NB * 4 + i];
    for (int i = tid; i < NB; i += blockDim.x) { smgt[i] = mask_gt[b * NB + i]; slbl[i] = gt_labels[b * NB + i]; }
    __syncthreads();
    int a = blockIdx.x * blockDim.x + tid;
    if (a >= NA) return;
    long long pos = (long long)b * NA + a;
    int c = g_cnt[pos];
    if (c == 0) { g_assigned[pos] = -1; g_norm_al[pos] = 0.f; return; }
    int jm; float met, ov;
    if (c == 1) {
        jm = g_candj[pos]; met = g_met_a[pos]; ov = g_ov_a[pos];
    } else {
        float ax = anc[a * 2 + 0], ay = anc[a * 2 + 1];
        const float4 pb = *(const float4*)(pd_bboxes + pos * 4);
        float bestov = -1.f; int bestj = 0;
        for (int j = 0; j < NB; j++) {
            float ovj = 0.f;
            if (smgt[j] > 0.f) {
                float gx1 = sgt[j * 4 + 0], gy1 = sgt[j * 4 + 1];
                float gx2 = sgt[j * 4 + 2], gy2 = sgt[j * 4 + 3];
                if (ax - gx1 > EPSF && ay - gy1 > EPSF && gx2 - ax > EPSF && gy2 - ay > EPSF)
                    ovj = fmaxf(ciou_f(gx1, gy1, gx2, gy2, pb.x, pb.y, pb.z, pb.w), 0.f);
            }
            if (ovj > bestov) { bestov = ovj; bestj = j; }
        }
        jm = bestj; ov = bestov;
        met = (ov > 0.f) ? pd_scores[pos * NC + slbl[jm]] * pow6(ov) : 0.f;
    }
    g_assigned[pos] = jm;
    g_norm_al[pos]  = met;
    atomicMax(&g_pos_align[b * NB + jm], __float_as_uint(met));
    atomicMax(&g_pos_over [b * NB + jm], __float_as_uint(ov));
}

// ---------------- kernel D: write all outputs (incl. full score rows) ----------------
#define D_ANCH 128
__global__ void k_out(const int* __restrict__ gt_labels, const float* __restrict__ gt_bboxes,
                      float* __restrict__ out) {
    int b = blockIdx.y;
    int base = blockIdx.x * D_ANCH;
    int tid = threadIdx.x;
    __shared__ int   scol [D_ANCH];   // score column (-1 if background)
    __shared__ float snorm[D_ANCH];
    const long long L = (long long)BS * NA;
    int nA = min(D_ANCH, NA - base);

    if (tid < nA) {
        int a = base + tid;
        long long pos = (long long)b * NA + a;
        int jm = g_assigned[pos];
        bool fg = (jm >= 0);
        int j0 = fg ? jm : 0;
        int label = gt_labels[b * NB + j0];
        const float4 gb = *(const float4*)(gt_bboxes + (b * NB + j0) * 4);
        out[pos] = (float)label;
        *(float4*)(out + L + pos * 4) = gb;
        out[L * 5 + L * NC + pos] = fg ? 1.f : 0.f;
        out[L * 6 + L * NC + pos] = (float)j0;
        float norm = 0.f;
        if (fg) {
            float pa = __uint_as_float(g_pos_align[b * NB + jm]);
            float po = __uint_as_float(g_pos_over [b * NB + jm]);
            norm = g_norm_al[pos] * po / (pa + EPSF);
        }
        scol [tid] = fg ? label : -1;
        snorm[tid] = norm;
    }
    __syncthreads();

    float* srow = out + L * 5 + ((long long)b * NA + base) * NC;
    int total = nA * NC;
    for (int k = tid; k < total; k += blockDim.x) {
        int la = k / NC, c = k - la * NC;
        srow[k] = (c == scol[la]) ? snorm[la] : 0.f;
    }
}

// ---------------- launch ----------------
extern "C" void kernel_launch(void* const* d_in, const int* in_sizes, int n_in,
                              void* d_out, int out_size) {
    const float* pd_scores = (const float*)d_in[0];
    const float* pd_bboxes = (const float*)d_in[1];
    const float* anc       = (const float*)d_in[2];
    const int*   gt_labels = (const int*)  d_in[3];
    const float* gt_bboxes = (const float*)d_in[4];
    const float* mask_gt   = (const float*)d_in[5];
    float* out = (float*)d_out;

    k_zeroScratch<<<512, 256>>>();
    k_bins<<<1, 1024>>>(anc);
    k_rows<<<BS * NB, 64>>>(pd_scores, pd_bboxes, anc, gt_labels, gt_bboxes, mask_gt);
    dim3 gridA((NA + 255) / 256, BS);
    k_resolve<<<gridA, 256>>>(pd_scores, pd_bboxes, anc, gt_labels, gt_bboxes, mask_gt);
    dim3 gridD((NA + D_ANCH - 1) / D_ANCH, BS);
    k_out<<<gridD, 256>>>(gt_labels, gt_bboxes, out);
}

// round 3
// speedup vs baseline: 1.3911x; 1.0308x over previous
#include <cuda_runtime.h>
#include <math.h>

#define BS 32
#define NA 8400
#define NC 80
#define NB 64
#define TOPK 13
#define CAP 640
#define EPSF 1e-9f
#define IOU_EPS 1e-7f
#define GW 32
#define GH 32
#define BININV 0.05f   // 1/20 px
#define TOUCH_MAX (BS * NB * TOPK)

// ---------------- scratch (static device globals) ----------------
__device__ int      g_bincnt[GW * GH];
__device__ int      g_bin_start[GW * GH + 1];
__device__ int      g_binoff[GW * GH];
__device__ int      g_abin[NA];
__device__ float    g_bax[NA];
__device__ float    g_bay[NA];
__device__ int      g_baid[NA];
__device__ int      g_cnt     [BS * NA];
__device__ int      g_candj   [BS * NA];
__device__ float    g_met_a   [BS * NA];
__device__ float    g_ov_a    [BS * NA];
__device__ int      g_assigned[BS * NA];
__device__ float    g_norm_al [BS * NA];
__device__ unsigned g_pos_align[BS * NB];   // float bits, >= 0
__device__ unsigned g_pos_over [BS * NB];
__device__ int      g_touch[TOUCH_MAX];
__device__ int      g_ntouch;

__device__ __forceinline__ float ciou_f(float gx1, float gy1, float gx2, float gy2,
                                        float px1, float py1, float px2, float py2) {
    float w1 = gx2 - gx1, h1 = gy2 - gy1 + IOU_EPS;
    float w2 = px2 - px1, h2 = py2 - py1 + IOU_EPS;
    float iw = fminf(gx2, px2) - fmaxf(gx1, px1);
    float ih = fminf(gy2, py2) - fmaxf(gy1, py1);
    float inter = fmaxf(iw, 0.f) * fmaxf(ih, 0.f);
    float uni = w1 * h1 + w2 * h2 - inter + IOU_EPS;
    float iou = inter / uni;
    float cw = fmaxf(gx2, px2) - fminf(gx1, px1);
    float ch = fmaxf(gy2, py2) - fminf(gy1, py1);
    float c2 = cw * cw + ch * ch + IOU_EPS;
    float dx = px1 + px2 - gx1 - gx2;
    float dy = py1 + py2 - gy1 - gy2;
    float rho2 = (dx * dx + dy * dy) * 0.25f;
    float dat = atanf(w2 / h2) - atanf(w1 / h1);
    float v = 0.4052847345693511f * dat * dat;
    float alpha = v / (v - iou + (1.0f + IOU_EPS));
    return iou - (rho2 / c2 + v * alpha);
}

__device__ __forceinline__ float pow6(float x) { float x2 = x * x; return x2 * x2 * x2; }

// ---------------- kernel Z: init scratch ----------------
__global__ void k_zero() {
    int i = blockIdx.x * blockDim.x + threadIdx.x;
    int stride = gridDim.x * blockDim.x;
    for (int k = i; k < BS * NA; k += stride) { g_cnt[k] = 0; g_assigned[k] = -1; }
    for (int k = i; k < BS * NB; k += stride) { g_pos_align[k] = 0u; g_pos_over[k] = 0u; }
    for (int k = i; k < GW * GH; k += stride) g_bincnt[k] = 0;
    if (i == 0) g_ntouch = 0;
}

// ---------------- kernel A1: count anchors per bin ----------------
__global__ void k_binCount(const float* __restrict__ anc) {
    int i = blockIdx.x * blockDim.x + threadIdx.x;
    if (i >= NA) return;
    float ax = anc[i * 2 + 0], ay = anc[i * 2 + 1];
    int bx = min(GW - 1, max(0, (int)(ax * BININV)));
    int by = min(GH - 1, max(0, (int)(ay * BININV)));
    int bin = by * GW + bx;
    g_abin[i] = bin;
    atomicAdd(&g_bincnt[bin], 1);
}

// ---------------- kernel A2: scan bins (1 block, 1024 threads) ----------------
__global__ void k_binScan() {
    __shared__ int s[GW * GH];
    int tid = threadIdx.x;
    int myc = g_bincnt[tid];
    s[tid] = myc;
    __syncthreads();
    for (int off = 1; off < GW * GH; off <<= 1) {
        int v = (tid >= off) ? s[tid - off] : 0;
        __syncthreads();
        s[tid] += v;
        __syncthreads();
    }
    g_bin_start[tid + 1] = s[tid];
    if (tid == 0) g_bin_start[0] = 0;
    g_binoff[tid] = s[tid] - myc;
}

// ---------------- kernel A3: scatter anchors into bins ----------------
__global__ void k_binScatter(const float* __restrict__ anc) {
    int i = blockIdx.x * blockDim.x + threadIdx.x;
    if (i >= NA) return;
    int bin = g_abin[i];
    int slot = atomicAdd(&g_binoff[bin], 1);
    g_baid[slot] = i;
    g_bax[slot] = anc[i * 2 + 0];
    g_bay[slot] = anc[i * 2 + 1];
}

// ---------------- kernel B: per-row candidates + top-13 + zero-fill + scatter ----------------
__global__ void k_rows(const float* __restrict__ pd_scores, const float* __restrict__ pd_bboxes,
                       const float* __restrict__ anc, const int* __restrict__ gt_labels,
                       const float* __restrict__ gt_bboxes, const float* __restrict__ mask_gt) {
    const int row = blockIdx.x;            // b*NB + j
    const int b = row >> 6, j = row & 63;
    const int tid = threadIdx.x;
    const int lane = tid & 31, wid = tid >> 5;

    __shared__ unsigned long long skey[CAP];
    __shared__ float sov[CAP];
    __shared__ int sP;
    __shared__ int sfidx[TOPK];
    __shared__ float sfmet[TOPK];
    __shared__ float sfovl[TOPK];
    __shared__ int skfill;
    __shared__ unsigned long long wbest[2];
    __shared__ int wslot[2];

    if (mask_gt[row] <= 0.f) return;

    if (tid == 0) sP = 0;
    __syncthreads();

    const float gx1 = gt_bboxes[row * 4 + 0], gy1 = gt_bboxes[row * 4 + 1];
    const float gx2 = gt_bboxes[row * 4 + 2], gy2 = gt_bboxes[row * 4 + 3];
    const int lbl = gt_labels[row];

    int bx_lo = min(GW - 1, max(0, (int)floorf(gx1 * BININV)));
    int bx_hi = min(GW - 1, max(0, (int)floorf(gx2 * BININV)));
    int by_lo = min(GH - 1, max(0, (int)floorf(gy1 * BININV)));
    int by_hi = min(GH - 1, max(0, (int)floorf(gy2 * BININV)));

    for (int by = by_lo; by <= by_hi; by++) {
        int s = g_bin_start[by * GW + bx_lo];
        int e = g_bin_start[by * GW + bx_hi + 1];
        for (int i = s + tid; i < e; i += 64) {
            float ax = g_bax[i], ay = g_bay[i];
            if (!(ax - gx1 > EPSF && ay - gy1 > EPSF && gx2 - ax > EPSF && gy2 - ay > EPSF)) continue;
            int a = g_baid[i];
            long long pos = (long long)b * NA + a;
            const float4 pb = __ldg((const float4*)(pd_bboxes + pos * 4));
            float ov = fmaxf(ciou_f(gx1, gy1, gx2, gy2, pb.x, pb.y, pb.z, pb.w), 0.f);
            float met = __ldg(pd_scores + pos * NC + lbl) * pow6(ov);
            if (met > 0.f) {
                int slot = atomicAdd(&sP, 1);
                if (slot < CAP) {
                    skey[slot] = ((unsigned long long)__float_as_uint(met) << 32)
                               | (unsigned)(0xFFFFFFFFu - (unsigned)a);
                    sov[slot] = ov;
                }
            }
        }
    }
    __syncthreads();
    int P = min(sP, CAP);
    int nsel = min(P, TOPK);

    for (int r = 0; r < nsel; r++) {
        unsigned long long best = 0; int bslot = -1;
        for (int i = tid; i < P; i += 64)
            if (skey[i] > best) { best = skey[i]; bslot = i; }
        for (int off = 16; off > 0; off >>= 1) {
            unsigned long long ob = __shfl_down_sync(0xFFFFFFFFu, best, off);
            int os = __shfl_down_sync(0xFFFFFFFFu, bslot, off);
            if (ob > best) { best = ob; bslot = os; }
        }
        if (lane == 0) { wbest[wid] = best; wslot[wid] = bslot; }
        __syncthreads();
        if (tid == 0) {
            unsigned long long bb = wbest[0]; int bs2 = wslot[0];
            if (wbest[1] > bb) { bb = wbest[1]; bs2 = wslot[1]; }
            sfidx[r] = (int)(0xFFFFFFFFu - (unsigned)(bb & 0xFFFFFFFFull));
            sfmet[r] = __uint_as_float((unsigned)(bb >> 32));
            sfovl[r] = sov[bs2];
            skey[bs2] = 0ull;
        }
        __syncthreads();
    }

    if (tid == 0) {
        int kfill = nsel;
        if (nsel < TOPK) {
            // top_k fills remaining slots with smallest-index zero-metric anchors;
            // they survive only if inside the gt box.
            int slots = nsel;
            int a = 0;
            while (slots < TOPK && a < NA) {
                bool ispos = false;
                for (int t = 0; t < nsel; t++)
                    if (sfidx[t] == a) { ispos = true; break; }
                if (!ispos) {
                    slots++;
                    float ax = anc[a * 2 + 0], ay = anc[a * 2 + 1];
                    if (ax - gx1 > EPSF && ay - gy1 > EPSF && gx2 - ax > EPSF && gy2 - ay > EPSF) {
                        sfidx[kfill] = a; sfmet[kfill] = 0.f; sfovl[kfill] = 0.f;
                        kfill++;
                    }
                }
                a++;
            }
        }
        skfill = kfill;
    }
    __syncthreads();

    if (tid < skfill) {
        int a = sfidx[tid];
        int pos = b * NA + a;
        int old = atomicAdd(&g_cnt[pos], 1);
        if (old == 0) {
            int t = atomicAdd(&g_ntouch, 1);
            g_touch[t] = pos;
        }
        g_candj[pos] = j;            // race only matters when cnt>1 (value unused then)
        g_met_a[pos] = sfmet[tid];
        g_ov_a[pos]  = sfovl[tid];
    }
}

// ---------------- kernel C: compact per-anchor resolution + pos maxima ----------------
__global__ void k_resolve(const float* __restrict__ pd_scores, const float* __restrict__ pd_bboxes,
                          const float* __restrict__ anc, const int* __restrict__ gt_labels,
                          const float* __restrict__ gt_bboxes, const float* __restrict__ mask_gt) {
    int i = blockIdx.x * blockDim.x + threadIdx.x;
    if (i >= g_ntouch) return;
    int pos = g_touch[i];
    int b = pos / NA;
    int a = pos - b * NA;
    int c = g_cnt[pos];
    int jm; float met, ov;
    if (c == 1) {
        jm = g_candj[pos]; met = g_met_a[pos]; ov = g_ov_a[pos];
    } else {
        // multi-gt anchor: argmax_j overlaps (first max wins), over ALL gts
        float ax = __ldg(anc + a * 2 + 0), ay = __ldg(anc + a * 2 + 1);
        const float4 pb = __ldg((const float4*)(pd_bboxes + (long long)pos * 4));
        float bestov = -1.f; int bestj = 0;
        for (int j = 0; j < NB; j++) {
            float ovj = 0.f;
            if (__ldg(mask_gt + b * NB + j) > 0.f) {
                const float4 g = __ldg((const float4*)(gt_bboxes + (b * NB + j) * 4));
                if (ax - g.x > EPSF && ay - g.y > EPSF && g.z - ax > EPSF && g.w - ay > EPSF)
                    ovj = fmaxf(ciou_f(g.x, g.y, g.z, g.w, pb.x, pb.y, pb.z, pb.w), 0.f);
            }
            if (ovj > bestov) { bestov = ovj; bestj = j; }
        }
        jm = bestj; ov = bestov;
        met = (ov > 0.f)
            ? __ldg(pd_scores + (long long)pos * NC + __ldg(gt_labels + b * NB + jm)) * pow6(ov)
            : 0.f;
    }
    g_assigned[pos] = jm;
    g_norm_al[pos]  = met;
    atomicMax(&g_pos_align[b * NB + jm], __float_as_uint(met));
    atomicMax(&g_pos_over [b * NB + jm], __float_as_uint(ov));
}

// ---------------- kernel D: write all outputs (float4 score rows) ----------------
#define D_ANCH 128
__global__ void k_out(const int* __restrict__ gt_labels, const float* __restrict__ gt_bboxes,
                      float* __restrict__ out) {
    int b = blockIdx.y;
    int base = blockIdx.x * D_ANCH;
    int tid = threadIdx.x;
    __shared__ int   scol [D_ANCH];   // score column (-1 if background)
    __shared__ float snorm[D_ANCH];
    const long long L = (long long)BS * NA;
    int nA = min(D_ANCH, NA - base);

    if (tid < nA) {
        int a = base + tid;
        long long pos = (long long)b * NA + a;
        int jm = g_assigned[pos];
        bool fg = (jm >= 0);
        int j0 = fg ? jm : 0;
        int label = gt_labels[b * NB + j0];
        const float4 gb = *(const float4*)(gt_bboxes + (b * NB + j0) * 4);
        out[pos] = (float)label;
        *(float4*)(out + L + pos * 4) = gb;
        out[L * 5 + L * NC + pos] = fg ? 1.f : 0.f;
        out[L * 6 + L * NC + pos] = (float)j0;
        float norm = 0.f;
        if (fg) {
            float pa = __uint_as_float(g_pos_align[b * NB + jm]);
            float po = __uint_as_float(g_pos_over [b * NB + jm]);
            norm = g_norm_al[pos] * po / (pa + EPSF);
        }
        scol [tid] = fg ? label : -1;
        snorm[tid] = norm;
    }
    __syncthreads();

    // score rows: NC=80 floats = 20 float4 per anchor
    float4* srow = (float4*)(out + L * 5 + ((long long)b * NA + base) * NC);
    int total = nA * (NC / 4);
    for (int k = tid; k < total; k += blockDim.x) {
        int la = k / (NC / 4), q = k - la * (NC / 4);
        float4 v = make_float4(0.f, 0.f, 0.f, 0.f);
        int col = scol[la];
        if ((col >> 2) == q) {
            float n = snorm[la];
            int r = col & 3;
            if (r == 0) v.x = n; else if (r == 1) v.y = n; else if (r == 2) v.z = n; else v.w = n;
        }
        srow[k] = v;
    }
}

// ---------------- launch ----------------
extern "C" void kernel_launch(void* const* d_in, const int* in_sizes, int n_in,
                              void* d_out, int out_size) {
    const float* pd_scores = (const float*)d_in[0];
    const float* pd_bboxes = (const float*)d_in[1];
    const float* anc       = (const float*)d_in[2];
    const int*   gt_labels = (const int*)  d_in[3];
    const float* gt_bboxes = (const float*)d_in[4];
    const float* mask_gt   = (const float*)d_in[5];
    float* out = (float*)d_out;

    k_zero<<<512, 256>>>();
    k_binCount<<<(NA + 255) / 256, 256>>>(anc);
    k_binScan<<<1, GW * GH>>>();
    k_binScatter<<<(NA + 255) / 256, 256>>>(anc);
    k_rows<<<BS * NB, 64>>>(pd_scores, pd_bboxes, anc, gt_labels, gt_bboxes, mask_gt);
    k_resolve<<<(TOUCH_MAX + 255) / 256, 256>>>(pd_scores, pd_bboxes, anc, gt_labels, gt_bboxes, mask_gt);
    dim3 gridD((NA + D_ANCH - 1) / D_ANCH, BS);
    k_out<<<gridD, 256>>>(gt_labels, gt_bboxes, out);
}